// round 6
// baseline (speedup 1.0000x reference)
#include <cuda_runtime.h>
#include <math.h>

// ---------------- problem constants ----------------
constexpr int N_NODES = 10000;
constexpr int N_EDGES = 160000;
constexpr int B       = 8;
constexpr int T_IN    = 12;
constexpr int HP      = 64;
constexpr int HV      = 32;
constexpr int CDIM    = 2 * HP + 1;   // 129
constexpr int NB      = N_NODES * B;  // 80000
constexpr int EB      = N_EDGES * B;  // 1280000
constexpr int VGRID   = EB / 256;     // 5000 blocks per branch

// ---------------- device scratch (static; no allocation) ----------------
__device__ float4       g_node[NB];     // per (node,b): P, R, S, Q
__device__ float        g_att[EB];      // a, then reused as ex
__device__ float        g_dsum[EB];     // sum_k diff*feature[src]
__device__ unsigned int g_amax[NB];     // ordered-uint encoded float max
__device__ float        g_den[NB];      // softmax denominator
__device__ float        g_gw[CDIM];     // ln2_g * attn_w
__device__ float        g_GC[2];        // [0]=sum(g*w), [1]=sum(b*w)
__device__ float        g_xv[2 * EB];   // [0..EB): x_up ; [EB..2EB): x_dn

// ---------------- ordered-float atomicMax helpers ----------------
__device__ __forceinline__ unsigned int f2ord(float f) {
    unsigned int u = __float_as_uint(f);
    return (u & 0x80000000u) ? ~u : (u | 0x80000000u);
}
__device__ __forceinline__ float ord2f(unsigned int u) {
    return (u & 0x80000000u) ? __uint_as_float(u & 0x7FFFFFFFu)
                             : __uint_as_float(~u);
}

// ---------------- prep: gw = ln2_g*attn_w; G = sum(gw); C = sum(ln2_b*attn_w) --------
__global__ void prep_kernel(const float* __restrict__ ln2g,
                            const float* __restrict__ ln2b,
                            const float* __restrict__ attnw) {
    __shared__ float sG[256];
    __shared__ float sC[256];
    int t = threadIdx.x;
    float gv = 0.f, cv = 0.f;
    if (t < CDIM) {
        float w = attnw[t];
        gv = ln2g[t] * w;
        cv = ln2b[t] * w;
        g_gw[t] = gv;
    }
    sG[t] = gv; sC[t] = cv;
    __syncthreads();
    for (int s = 128; s > 0; s >>= 1) {
        if (t < s) { sG[t] += sG[t + s]; sC[t] += sC[t + s]; }
        __syncthreads();
    }
    if (t == 0) { g_GC[0] = sG[0]; g_GC[1] = sC[0]; }
}

// ---------------- init: zero pred, den, amax ----------------
__global__ void init_kernel(float* __restrict__ out) {
    int t = blockIdx.x * blockDim.x + threadIdx.x;
    if (t < NB) {
        out[t]    = 0.f;
        g_den[t]  = 0.f;
        g_amax[t] = 0u;
    }
}

// ---------------- node kernel: fold z into (P,R,S,Q) ----------------
__global__ __launch_bounds__(128)
void node_kernel(const float* __restrict__ feat,
                 const float* __restrict__ fcw) {
    __shared__ float sw[HP * T_IN];   // 768
    __shared__ float sgw[2 * HP];     // 128
    int tid = threadIdx.x;
    for (int i = tid; i < HP * T_IN; i += blockDim.x) sw[i]  = fcw[i];
    for (int i = tid; i < 2 * HP;    i += blockDim.x) sgw[i] = g_gw[i];
    __syncthreads();

    int t = blockIdx.x * blockDim.x + tid;
    if (t >= NB) return;

    float fr[T_IN];
    {
        const float4* f4 = reinterpret_cast<const float4*>(feat) + (size_t)t * 3;
        float4 a0 = f4[0], a1 = f4[1], a2 = f4[2];
        fr[0]=a0.x; fr[1]=a0.y; fr[2]=a0.z;  fr[3]=a0.w;
        fr[4]=a1.x; fr[5]=a1.y; fr[6]=a1.z;  fr[7]=a1.w;
        fr[8]=a2.x; fr[9]=a2.y; fr[10]=a2.z; fr[11]=a2.w;
    }

    float P = 0.f, R = 0.f, S = 0.f, Q = 0.f;
#pragma unroll
    for (int h = 0; h < HP; ++h) {
        float z = 0.f;
#pragma unroll
        for (int k = 0; k < T_IN; ++k) z = fmaf(sw[h * T_IN + k], fr[k], z);
        P = fmaf(z, sgw[h], P);
        R = fmaf(z, sgw[HP + h], R);
        S += z;
        Q = fmaf(z, z, Q);
    }
    g_node[t] = make_float4(P, R, S, Q);
}

// ---------------- velocity kernel: 1 thread = 1 (edge,batch) item, 1 branch ---------
// branch selected by blockIdx.x; both branches in one launch.
struct VP {
    const float *up, *dn;
    const float *w1a, *b1a, *lga, *lba, *w2a, *b2a;
    const float *w1b, *b1b, *lgb, *lbb, *w2b, *b2b;
};

__global__ __launch_bounds__(256)
void vel_kernel(VP p) {
    int bx = blockIdx.x;
    bool dnb = bx >= VGRID;
    const float* inp = dnb ? p.dn  : p.up;
    const float* w1  = dnb ? p.w1b : p.w1a;
    const float* b1  = dnb ? p.b1b : p.b1a;
    const float* lg  = dnb ? p.lgb : p.lga;
    const float* lb  = dnb ? p.lbb : p.lba;
    const float* w2  = dnb ? p.w2b : p.w2a;
    const float* b2  = dnb ? p.b2b : p.b2a;

    __shared__ float4 sw[HV * 3];    // weight rows, 3 float4 each (1.5 KB)
    __shared__ float4 se[HV];        // (b1, lg, lb, w2) per hidden unit
    __shared__ float  sb2;
    int tid = threadIdx.x;
    if (tid < HV * 3) sw[tid] = reinterpret_cast<const float4*>(w1)[tid];
    if (tid >= 128 && tid < 128 + HV) {
        int j = tid - 128;
        se[j] = make_float4(b1[j], lg[j], lb[j], w2[j]);
    }
    if (tid == 224) sb2 = b2[0];
    __syncthreads();

    int t = (bx - (dnb ? VGRID : 0)) * 256 + tid;   // item index in [0, EB)
    const float4* f4 = reinterpret_cast<const float4*>(inp) + (size_t)t * 3;
    float4 i0 = f4[0], i1 = f4[1], i2 = f4[2];

    float h[HV];
    float sum = 0.f, q = 0.f;
#pragma unroll
    for (int j = 0; j < HV; ++j) {
        float4 wa = sw[3 * j], wb = sw[3 * j + 1], wc = sw[3 * j + 2];
        float a = se[j].x;
        a = fmaf(wa.x, i0.x, a); a = fmaf(wa.y, i0.y, a);
        a = fmaf(wa.z, i0.z, a); a = fmaf(wa.w, i0.w, a);
        a = fmaf(wb.x, i1.x, a); a = fmaf(wb.y, i1.y, a);
        a = fmaf(wb.z, i1.z, a); a = fmaf(wb.w, i1.w, a);
        a = fmaf(wc.x, i2.x, a); a = fmaf(wc.y, i2.y, a);
        a = fmaf(wc.z, i2.z, a); a = fmaf(wc.w, i2.w, a);
        h[j] = a;
        sum += a;
        q = fmaf(a, a, q);
    }
    float m   = sum * (1.0f / HV);
    float var = fmaf(-m, m, q * (1.0f / HV));
    float inv = rsqrtf(var + 1e-5f);

    float s = sb2;
#pragma unroll
    for (int j = 0; j < HV; ++j) {
        float4 e = se[j];
        float y = fmaf((h[j] - m) * inv, e.y, e.z);
        y = fmaxf(y, 0.f);
        s = fmaf(y, e.w, s);
    }
    float o = __fdividef(1.0f, 1.0f + __expf(-s));
    g_xv[(dnb ? EB : 0) + t] = o;
}

// ---------------- edge attention + diffusion kernel ----------------
__global__ __launch_bounds__(256)
void edgeA_kernel(const float* __restrict__ dist,
                  const float* __restrict__ alpha,
                  const float* __restrict__ feat,
                  const int* __restrict__ src,
                  const int* __restrict__ dst,
                  const float* __restrict__ l3w,
                  const float* __restrict__ l3b) {
    __shared__ float c[7];
    if (threadIdx.x == 0) {
        c[0] = l3w[0]; c[1] = l3w[1]; c[2] = l3w[2]; c[3] = l3b[0];
        c[4] = g_gw[128]; c[5] = g_GC[0]; c[6] = g_GC[1];
    }
    __syncthreads();

    int t = blockIdx.x * 256 + threadIdx.x;
    if (t >= EB) return;
    int e = t >> 3;
    int b = t & 7;

    float xup = g_xv[t];
    float xdn = g_xv[EB + t];
    float al  = alpha[e];

    float xv = c[0] * xup + c[1] * xdn + c[2] * al + c[3];
    float v = (xv > 0.f) ? (xv + __logf(1.0f + __expf(-xv)))
                         : __logf(1.0f + __expf(xv));
    v = fminf(v, 3.0f);
    float Tt = __fdividef(dist[e], v + 1e-5f);

    float Tidx = fminf(fmaxf(rintf(Tt * 0.1f), 0.0f), 11.0f);
    int   n    = T_IN - (int)Tidx;                  // 1..12
    float alc  = fminf(fmaxf(al, 0.f), 1.f);
    float F    = __fdividef(1.0f, 1.0f + alc * Tt);
    float omF  = 1.0f - F;

    int se = src[e];
    int de = dst[e];

    float f[T_IN];
    {
        const float4* f4 = reinterpret_cast<const float4*>(feat)
                           + ((size_t)se * B + b) * 3;
        float4 q0 = f4[0], q1 = f4[1], q2 = f4[2];
        f[0]=q0.x; f[1]=q0.y; f[2]=q0.z;  f[3]=q0.w;
        f[4]=q1.x; f[5]=q1.y; f[6]=q1.z;  f[7]=q1.w;
        f[8]=q2.x; f[9]=q2.y; f[10]=q2.z; f[11]=q2.w;
    }
    float acc = 0.f, pw = 0.f;
#pragma unroll
    for (int k = T_IN - 1; k >= 0; --k) {
        if (k == n - 1) pw = F;
        if (k <= n - 1) { acc = fmaf(pw, f[k], acc); pw *= omF; }
    }

    float4 ns = g_node[se * B + b];
    float4 nd = g_node[de * B + b];
    float Ssum = ns.z + nd.z + Tt;
    float m    = Ssum * (1.0f / 129.0f);
    float q    = ns.w + nd.w + Tt * Tt;
    float var  = q * (1.0f / 129.0f) - m * m;
    float dot  = ns.x + nd.y + Tt * c[4];
    float a    = (dot - m * c[5]) * rsqrtf(var + 1e-5f) + c[6];
    a = (a >= 0.f) ? a : 0.01f * a;                 // leaky_relu

    g_att[t]  = a;
    g_dsum[t] = acc;
    atomicMax(&g_amax[se * B + b], f2ord(a));
}

// ---------------- edge pass 2: ex = exp(a - amax[src]); den[src] += ex --------------
__global__ __launch_bounds__(256)
void edge2_kernel(const int* __restrict__ src) {
    int t = blockIdx.x * 256 + threadIdx.x;
    if (t >= EB) return;
    int e = t >> 3, b = t & 7;
    int se = src[e];
    float amax = ord2f(g_amax[se * B + b]);
    float ex = __expf(g_att[t] - amax);
    g_att[t] = ex;
    atomicAdd(&g_den[se * B + b], ex);
}

// ---------------- edge pass 3: pred[dst] += ex/den[src] * dsum ----------------
__global__ __launch_bounds__(256)
void edge3_kernel(const int* __restrict__ src, const int* __restrict__ dst,
                  float* __restrict__ out) {
    int t = blockIdx.x * 256 + threadIdx.x;
    if (t >= EB) return;
    int e = t >> 3, b = t & 7;
    int se = src[e];
    int de = dst[e];
    float val = __fdividef(g_att[t], g_den[se * B + b]) * g_dsum[t];
    atomicAdd(&out[de * B + b], val);
}

// ---------------- launch ----------------
extern "C" void kernel_launch(void* const* d_in, const int* in_sizes, int n_in,
                              void* d_out, int out_size) {
    bool sig_order = (n_in >= 6 && in_sizes[5] == HP * T_IN);   // fc_w=768 at idx 5

    int i_src, i_dst, i_alpha, i_fcw, i_ln2g, i_ln2b, i_attnw;
    int i_l11w, i_l11b, i_ln11g, i_ln11b, i_l12w, i_l12b;
    int i_l21w, i_l21b, i_ln21g, i_ln21b, i_l22w, i_l22b, i_l3w, i_l3b;

    if (!sig_order) {
        i_src = 4;  i_dst = 5;  i_alpha = 6;  i_fcw = 7;
        i_ln2g = 8; i_ln2b = 9; i_attnw = 10;
        i_l11w = 11; i_l11b = 12; i_ln11g = 13; i_ln11b = 14; i_l12w = 15; i_l12b = 16;
        i_l21w = 17; i_l21b = 18; i_ln21g = 19; i_ln21b = 20; i_l22w = 21; i_l22b = 22;
        i_l3w = 23;  i_l3b = 24;
    } else {
        i_alpha = 4; i_fcw = 5;
        i_ln2g = 6;  i_ln2b = 7; i_attnw = 8;
        i_l11w = 9;  i_l11b = 10; i_ln11g = 11; i_ln11b = 12; i_l12w = 13; i_l12b = 14;
        i_l21w = 15; i_l21b = 16; i_ln21g = 17; i_ln21b = 18; i_l22w = 19; i_l22b = 20;
        i_l3w = 21;  i_l3b = 22;  i_src = 23;   i_dst = 24;
    }

    const float* feat  = (const float*)d_in[0];
    const float* up    = (const float*)d_in[1];
    const float* dn    = (const float*)d_in[2];
    const float* dist  = (const float*)d_in[3];
    const float* alpha = (const float*)d_in[i_alpha];
    const int*   src   = (const int*)d_in[i_src];
    const int*   dst   = (const int*)d_in[i_dst];
    float* out = (float*)d_out;

    prep_kernel<<<1, 256>>>((const float*)d_in[i_ln2g],
                            (const float*)d_in[i_ln2b],
                            (const float*)d_in[i_attnw]);

    init_kernel<<<(NB + 255) / 256, 256>>>(out);

    node_kernel<<<NB / 128, 128>>>(feat, (const float*)d_in[i_fcw]);

    VP vp;
    vp.up  = up;  vp.dn  = dn;
    vp.w1a = (const float*)d_in[i_l11w]; vp.b1a = (const float*)d_in[i_l11b];
    vp.lga = (const float*)d_in[i_ln11g]; vp.lba = (const float*)d_in[i_ln11b];
    vp.w2a = (const float*)d_in[i_l12w]; vp.b2a = (const float*)d_in[i_l12b];
    vp.w1b = (const float*)d_in[i_l21w]; vp.b1b = (const float*)d_in[i_l21b];
    vp.lgb = (const float*)d_in[i_ln21g]; vp.lbb = (const float*)d_in[i_ln21b];
    vp.w2b = (const float*)d_in[i_l22w]; vp.b2b = (const float*)d_in[i_l22b];

    vel_kernel<<<2 * VGRID, 256>>>(vp);

    edgeA_kernel<<<EB / 256, 256>>>(dist, alpha, feat, src, dst,
                                    (const float*)d_in[i_l3w],
                                    (const float*)d_in[i_l3b]);
    edge2_kernel<<<EB / 256, 256>>>(src);
    edge3_kernel<<<EB / 256, 256>>>(src, dst, out);
}